// round 3
// baseline (speedup 1.0000x reference)
#include <cuda_runtime.h>
#include <stdint.h>

#define NC    32
#define KC    16
#define DSUB  128
#define INF   4096
#define OF    2048
#define MAXTOK 2048

typedef unsigned long long ull;

__device__ float         g_lut[NC * KC * OF];
__device__ unsigned char g_idx[MAXTOK * NC];

// ---- packed f32x2 helpers --------------------------------------------------
__device__ __forceinline__ ull pk2(float x, float y) {
    ull r; asm("mov.b64 %0, {%1,%2};" : "=l"(r) : "f"(x), "f"(y)); return r;
}
__device__ __forceinline__ void upk2(ull v, float& x, float& y) {
    asm("mov.b64 {%0,%1}, %2;" : "=f"(x), "=f"(y) : "l"(v));
}
__device__ __forceinline__ ull fma2(ull a, ull b, ull c) {
    ull d; asm("fma.rn.f32x2 %0, %1, %2, %3;" : "=l"(d) : "l"(a), "l"(b), "l"(c)); return d;
}
__device__ __forceinline__ ull add2(ull a, ull b) {
    ull d; asm("add.rn.f32x2 %0, %1, %2;" : "=l"(d) : "l"(a), "l"(b)); return d;
}

// ---------------------------------------------------------------------------
// K1: lut[c,k,o] = sum_d cent[c,k,d] * weight[c,d,o]
// grid (OF/128, NC), 256 threads. Block splits d into two halves of 64
// (half = tid>>7), o-tile 128 (col = tid&127); halves combined via smem.
// 512 blocks x 8 warps -> ~24 warps/SM -> enough LDGs in flight for HBM.
// ---------------------------------------------------------------------------
__global__ __launch_bounds__(256) void lut_kernel(const float* __restrict__ cent,
                                                  const float* __restrict__ weight)
{
    __shared__ float cst[DSUB * KC];   // cst[d][k]   (8 KB)
    __shared__ float red[KC * 128];    // partial sums (8 KB)
    const int c    = blockIdx.y;
    const int tid  = threadIdx.x;
    const int half = tid >> 7;         // 0 or 1 : d-range
    const int col  = tid & 127;        // o within tile

    for (int i = tid; i < KC * DSUB; i += 256) {
        int k = i >> 7, d = i & 127;
        cst[d * KC + k] = cent[(c * KC + k) * DSUB + d];
    }
    __syncthreads();

    const int o = blockIdx.x * 128 + col;
    ull acc[8];
#pragma unroll
    for (int kk = 0; kk < 8; kk++) acc[kk] = 0ull;

    const float* wp = weight + (size_t)c * DSUB * OF + o;
    const int dbase = half * 64;
    for (int d0 = dbase; d0 < dbase + 64; d0 += 8) {
        float w[8];
#pragma unroll
        for (int i = 0; i < 8; i++) w[i] = wp[(size_t)(d0 + i) * OF];
#pragma unroll
        for (int i = 0; i < 8; i++) {
            ull wv = pk2(w[i], w[i]);
            const float4* cp = (const float4*)&cst[(d0 + i) * KC];
#pragma unroll
            for (int q = 0; q < 4; q++) {
                float4 cv = cp[q];
                acc[q * 2 + 0] = fma2(pk2(cv.x, cv.y), wv, acc[q * 2 + 0]);
                acc[q * 2 + 1] = fma2(pk2(cv.z, cv.w), wv, acc[q * 2 + 1]);
            }
        }
    }

    if (half == 1) {
#pragma unroll
        for (int kk = 0; kk < 8; kk++) {
            float v0, v1; upk2(acc[kk], v0, v1);
            red[(kk * 2 + 0) * 128 + col] = v0;
            red[(kk * 2 + 1) * 128 + col] = v1;
        }
    }
    __syncthreads();
    if (half == 0) {
#pragma unroll
        for (int kk = 0; kk < 8; kk++) {
            float v0, v1; upk2(acc[kk], v0, v1);
            v0 += red[(kk * 2 + 0) * 128 + col];
            v1 += red[(kk * 2 + 1) * 128 + col];
            g_lut[(size_t)(c * KC + kk * 2 + 0) * OF + o] = v0;
            g_lut[(size_t)(c * KC + kk * 2 + 1) * OF + o] = v1;
        }
    }
}

// ---------------------------------------------------------------------------
// K2: idx[token][c] = argmin_k ( c2[k] - 2 * <x_sub, cent_k> )  (unchanged)
// ---------------------------------------------------------------------------
__global__ __launch_bounds__(128) void idx_kernel(const float* __restrict__ x,
                                                  const float* __restrict__ cent)
{
    extern __shared__ float sm[];
    float* xs  = sm;                      // 128 * 129
    float* cst = sm + 128 * 129;          // DSUB * KC
    float* c2p = cst + DSUB * KC;         // 16 * 8
    float* c2s = c2p + 16 * 8;            // 16

    const int c   = blockIdx.y;
    const int tb  = blockIdx.x * 128;
    const int tid = threadIdx.x;

    for (int i = tid; i < KC * DSUB; i += 128) {
        int k = i >> 7, d = i & 127;
        cst[d * KC + k] = cent[(c * KC + k) * DSUB + d];
    }
    for (int i = tid; i < 128 * DSUB / 4; i += 128) {
        int e = i * 4, row = e >> 7, col = e & 127;
        float4 v = *(const float4*)&x[(size_t)(tb + row) * INF + c * DSUB + col];
        float* dst = &xs[row * 129 + col];
        dst[0] = v.x; dst[1] = v.y; dst[2] = v.z; dst[3] = v.w;
    }
    __syncthreads();

    {
        int k = tid >> 3, part = tid & 7;
        float s = 0.f;
        for (int d = part * 16; d < part * 16 + 16; d++) {
            float cv = cst[d * KC + k];
            s = fmaf(cv, cv, s);
        }
        c2p[k * 8 + part] = s;
    }
    __syncthreads();
    if (tid < 16) {
        float s = 0.f;
        for (int p = 0; p < 8; p++) s += c2p[tid * 8 + p];
        c2s[tid] = s;
    }
    __syncthreads();

    ull acc[8];
#pragma unroll
    for (int kk = 0; kk < 8; kk++) acc[kk] = 0ull;

    const float* xr = &xs[tid * 129];
#pragma unroll 4
    for (int d = 0; d < DSUB; d++) {
        float xv = xr[d];
        ull xp = pk2(xv, xv);
        const float4* cp = (const float4*)&cst[d * KC];
#pragma unroll
        for (int q = 0; q < 4; q++) {
            float4 cv = cp[q];
            acc[q * 2 + 0] = fma2(pk2(cv.x, cv.y), xp, acc[q * 2 + 0]);
            acc[q * 2 + 1] = fma2(pk2(cv.z, cv.w), xp, acc[q * 2 + 1]);
        }
    }

    float dot[KC];
#pragma unroll
    for (int kk = 0; kk < 8; kk++) upk2(acc[kk], dot[kk * 2], dot[kk * 2 + 1]);

    float best = 1e30f, second = 1e30f;
    int bi = 0, si = 0;
#pragma unroll
    for (int k = 0; k < KC; k++) {
        float v = c2s[k] - 2.f * dot[k];
        if (v < best)        { second = best; si = bi; best = v; bi = k; }
        else if (v < second) { second = v; si = k; }
    }
    if (second - best < 1e-2f) {
        double vb = 0.0, vs = 0.0;
        for (int d = 0; d < DSUB; d++) {
            double xv = (double)xr[d];
            double cb = (double)cst[d * KC + bi];
            double cs = (double)cst[d * KC + si];
            vb += cb * (cb - 2.0 * xv);
            vs += cs * (cs - 2.0 * xv);
        }
        if (vs < vb || (vs == vb && si < bi)) bi = si;
    }
    g_idx[(size_t)(tb + tid) * NC + c] = (unsigned char)bi;
}

// ---------------------------------------------------------------------------
// K3: out[n,o] = bias[o] + sum_c lut[c, idx[n][c], o]
// 512 threads (16 warps/SM) to saturate the smem crossbar.
// ---------------------------------------------------------------------------
__global__ __launch_bounds__(512) void gather_kernel(float* __restrict__ out,
                                                     const float* __restrict__ bias)
{
    extern __shared__ float sm[];
    float*         lut_s = sm;                                  // NC*KC*64
    unsigned char* idx_s = (unsigned char*)(sm + NC * KC * 64); // 256*32 B

    const int ob  = blockIdx.x * 64;
    const int tb  = blockIdx.y * 256;
    const int tid = threadIdx.x;

    for (int i = tid; i < NC * KC * 64 / 4; i += 512) {
        int row = i >> 4;
        int col = (i & 15) * 4;
        float4 v = *(const float4*)&g_lut[(size_t)row * OF + ob + col];
        *(float4*)&lut_s[row * 64 + col] = v;
    }
    {
        const uint4* src = (const uint4*)&g_idx[(size_t)tb * NC];
        uint4* dst = (uint4*)idx_s;
        for (int i = tid; i < (256 * NC) / 16; i += 512) dst[i] = src[i];
    }
    __syncthreads();

    const int oq = tid & 15;   // o-quad: columns oq*4 .. oq*4+3
    const int tg = tid >> 4;   // token group 0..31
    const float4 bv = *(const float4*)&bias[ob + oq * 4];

    for (int t = tg; t < 256; t += 32) {
        uint4 a = *(const uint4*)&idx_s[t * NC];
        uint4 b = *(const uint4*)&idx_s[t * NC + 16];
        unsigned int iw[8] = {a.x, a.y, a.z, a.w, b.x, b.y, b.z, b.w};
        ull s0 = 0ull, s1 = 0ull, s2 = 0ull, s3 = 0ull;
#pragma unroll
        for (int c = 0; c < NC; c++) {
            unsigned int k = (iw[c >> 2] >> ((c & 3) * 8)) & 0xFFu;
            float4 v = *(const float4*)&lut_s[(c * KC + k) * 64 + oq * 4];
            if (c & 1) { s2 = add2(s2, pk2(v.x, v.y)); s3 = add2(s3, pk2(v.z, v.w)); }
            else       { s0 = add2(s0, pk2(v.x, v.y)); s1 = add2(s1, pk2(v.z, v.w)); }
        }
        s0 = add2(s0, s2);
        s1 = add2(s1, s3);
        float4 r;
        float a0, a1; upk2(s0, a0, a1);
        float a2, a3; upk2(s1, a2, a3);
        r.x = a0 + bv.x; r.y = a1 + bv.y; r.z = a2 + bv.z; r.w = a3 + bv.w;
        *(float4*)&out[(size_t)(tb + t) * OF + ob + oq * 4] = r;
    }
}

// ---------------------------------------------------------------------------
extern "C" void kernel_launch(void* const* d_in, const int* in_sizes, int n_in,
                              void* d_out, int out_size)
{
    const float* x      = (const float*)d_in[0];
    const float* cent   = (const float*)d_in[1];
    const float* weight = (const float*)d_in[2];
    const float* bias   = (const float*)d_in[4];
    float* out = (float*)d_out;

    const int ntok = in_sizes[0] / INF;

    const int IDX_SMEM = (128 * 129 + DSUB * KC + 16 * 8 + 16) * (int)sizeof(float);
    const int G_SMEM   = NC * KC * 64 * (int)sizeof(float) + 256 * NC;

    cudaFuncSetAttribute(idx_kernel,    cudaFuncAttributeMaxDynamicSharedMemorySize, IDX_SMEM);
    cudaFuncSetAttribute(gather_kernel, cudaFuncAttributeMaxDynamicSharedMemorySize, G_SMEM);

    lut_kernel<<<dim3(OF / 128, NC), 256>>>(cent, weight);
    idx_kernel<<<dim3(ntok / 128, NC), 128, IDX_SMEM>>>(x, cent);
    gather_kernel<<<dim3(OF / 64, ntok / 256), 512, G_SMEM>>>(out, bias);
}

// round 4
// speedup vs baseline: 1.5285x; 1.5285x over previous
#include <cuda_runtime.h>
#include <stdint.h>

#define NC    32
#define KC    16
#define DSUB  128
#define INF   4096
#define OF    2048
#define MAXTOK 2048

typedef unsigned long long ull;

__device__ float         g_lut[NC * KC * OF];
__device__ unsigned char g_idx[MAXTOK * NC];

// ---- packed f32x2 helpers --------------------------------------------------
__device__ __forceinline__ ull pk2(float x, float y) {
    ull r; asm("mov.b64 %0, {%1,%2};" : "=l"(r) : "f"(x), "f"(y)); return r;
}
__device__ __forceinline__ void upk2(ull v, float& x, float& y) {
    asm("mov.b64 {%0,%1}, %2;" : "=f"(x), "=f"(y) : "l"(v));
}
__device__ __forceinline__ ull fma2(ull a, ull b, ull c) {
    ull d; asm("fma.rn.f32x2 %0, %1, %2, %3;" : "=l"(d) : "l"(a), "l"(b), "l"(c)); return d;
}

// ---------------------------------------------------------------------------
// K1: lut[c,k,o] = sum_d cent[c,k,d] * weight[c,d,o]
// grid (OF/256, NC), 128 threads; thread = 2 o-cols (float2), full d range,
// 16-deep LDG.64 batch (128 B in flight per thread) for DRAM latency hiding.
// f32x2 acc paired over o => per-column accumulation order == R1 (bitwise).
// ---------------------------------------------------------------------------
__global__ __launch_bounds__(128) void lut_kernel(const float* __restrict__ cent,
                                                  const float* __restrict__ weight)
{
    __shared__ float cst[DSUB * KC];   // cst[d][k]
    const int c   = blockIdx.y;
    const int tid = threadIdx.x;

    for (int i = tid; i < KC * DSUB; i += 128) {
        int k = i >> 7, d = i & 127;
        cst[d * KC + k] = cent[(c * KC + k) * DSUB + d];
    }
    __syncthreads();

    const int o = blockIdx.x * 256 + tid * 2;
    ull acc[KC];
#pragma unroll
    for (int k = 0; k < KC; k++) acc[k] = 0ull;

    const float* wp = weight + (size_t)c * DSUB * OF + o;
    for (int d0 = 0; d0 < DSUB; d0 += 16) {
        float2 w[16];
#pragma unroll
        for (int i = 0; i < 16; i++) w[i] = *(const float2*)(wp + (size_t)(d0 + i) * OF);
#pragma unroll
        for (int i = 0; i < 16; i++) {
            ull wv = pk2(w[i].x, w[i].y);
            const float* cp = &cst[(d0 + i) * KC];
#pragma unroll
            for (int k = 0; k < KC; k++) {
                float cv = cp[k];
                acc[k] = fma2(pk2(cv, cv), wv, acc[k]);
            }
        }
    }
#pragma unroll
    for (int k = 0; k < KC; k++) {
        float v0, v1; upk2(acc[k], v0, v1);
        *(float2*)&g_lut[(size_t)(c * KC + k) * OF + o] = make_float2(v0, v1);
    }
}

// ---------------------------------------------------------------------------
// K2: idx — EXACT Round-1 version (part of the known-111us baseline).
// ---------------------------------------------------------------------------
__global__ void idx_kernel(const float* __restrict__ x,
                           const float* __restrict__ cent)
{
    extern __shared__ float sm[];
    float* xs  = sm;                      // 128 * 129
    float* cst = sm + 128 * 129;          // DSUB * KC (transposed)
    float* c2p = cst + DSUB * KC;         // 16 * 8 partials
    float* c2s = c2p + 16 * 8;            // 16

    const int c   = blockIdx.y;
    const int tb  = blockIdx.x * 128;
    const int tid = threadIdx.x;

    for (int i = tid; i < KC * DSUB; i += 128) {
        int k = i >> 7, d = i & 127;
        cst[d * KC + k] = cent[(c * KC + k) * DSUB + d];
    }
    for (int i = tid; i < 128 * DSUB / 4; i += 128) {
        int e   = i * 4;
        int row = e >> 7;
        int col = e & 127;
        float4 v = *(const float4*)&x[(size_t)(tb + row) * INF + c * DSUB + col];
        float* dst = &xs[row * 129 + col];
        dst[0] = v.x; dst[1] = v.y; dst[2] = v.z; dst[3] = v.w;
    }
    __syncthreads();

    {
        int k = tid >> 3, part = tid & 7;
        float s = 0.f;
        for (int d = part * 16; d < part * 16 + 16; d++) {
            float cv = cst[d * KC + k];
            s = fmaf(cv, cv, s);
        }
        c2p[k * 8 + part] = s;
    }
    __syncthreads();
    if (tid < 16) {
        float s = 0.f;
        for (int p = 0; p < 8; p++) s += c2p[tid * 8 + p];
        c2s[tid] = s;
    }
    __syncthreads();

    float acc[KC];
#pragma unroll
    for (int k = 0; k < KC; k++) acc[k] = 0.f;

    const float* xr = &xs[tid * 129];
#pragma unroll 2
    for (int d = 0; d < DSUB; d++) {
        float xv = xr[d];
#pragma unroll
        for (int k = 0; k < KC; k++)
            acc[k] = fmaf(xv, cst[d * KC + k], acc[k]);
    }

    float best = 1e30f, second = 1e30f;
    int bi = 0, si = 0;
#pragma unroll
    for (int k = 0; k < KC; k++) {
        float v = c2s[k] - 2.f * acc[k];
        if (v < best)        { second = best; si = bi; best = v; bi = k; }
        else if (v < second) { second = v; si = k; }
    }
    if (second - best < 1e-2f) {
        double vb = 0.0, vs = 0.0;
        for (int d = 0; d < DSUB; d++) {
            double xv = (double)xr[d];
            double cb = (double)cst[d * KC + bi];
            double cs = (double)cst[d * KC + si];
            vb += cb * (cb - 2.0 * xv);
            vs += cs * (cs - 2.0 * xv);
        }
        if (vs < vb || (vs == vb && si < bi)) bi = si;
    }
    g_idx[(size_t)(tb + tid) * NC + c] = (unsigned char)bi;
}

// ---------------------------------------------------------------------------
// K3: out[n,o] = bias[o] + sum_c lut[c, idx[n][c], o]
// o-tile 32 -> smem 72 KB -> 3 CTAs/SM (24 warps/SM) hides LDS latency.
// warp = token, lane = one o column; LDS.32 gathers are conflict-free.
// Accumulation order (even-c sum + odd-c sum) + bias == R1 (bitwise).
// ---------------------------------------------------------------------------
__global__ __launch_bounds__(256) void gather_kernel(float* __restrict__ out,
                                                     const float* __restrict__ bias)
{
    extern __shared__ float sm[];
    float*         lut_s = sm;                                  // NC*KC*32 floats (64 KB)
    unsigned char* idx_s = (unsigned char*)(sm + NC * KC * 32); // 256*32 B (8 KB)

    const int ob  = blockIdx.x * 32;
    const int tb  = blockIdx.y * 256;
    const int tid = threadIdx.x;

    // stage lut slice: 512 rows x 32 floats
    for (int i = tid; i < NC * KC * 32 / 4; i += 256) {
        int row = i >> 3;
        int col = (i & 7) * 4;
        float4 v = *(const float4*)&g_lut[(size_t)row * OF + ob + col];
        *(float4*)&lut_s[row * 32 + col] = v;
    }
    // stage idx tile: 8 KB
    {
        const uint4* src = (const uint4*)&g_idx[(size_t)tb * NC];
        uint4* dst = (uint4*)idx_s;
        for (int i = tid; i < (256 * NC) / 16; i += 256) dst[i] = src[i];
    }
    __syncthreads();

    const int oi = tid & 31;   // lane = o column
    const int tg = tid >> 5;   // warp = token group 0..7
    const float bv = bias[ob + oi];

    for (int t = tg; t < 256; t += 8) {
        uint4 a = *(const uint4*)&idx_s[t * NC];
        uint4 b = *(const uint4*)&idx_s[t * NC + 16];
        unsigned int iw[8] = {a.x, a.y, a.z, a.w, b.x, b.y, b.z, b.w};
        float s0 = 0.f, s1 = 0.f;
#pragma unroll
        for (int c = 0; c < NC; c++) {
            unsigned int k = (iw[c >> 2] >> ((c & 3) * 8)) & 0xFFu;
            float v = lut_s[(c * KC + k) * 32 + oi];
            if (c & 1) s1 += v;
            else       s0 += v;
        }
        out[(size_t)(tb + t) * OF + ob + oi] = s0 + s1 + bv;
    }
}

// ---------------------------------------------------------------------------
extern "C" void kernel_launch(void* const* d_in, const int* in_sizes, int n_in,
                              void* d_out, int out_size)
{
    const float* x      = (const float*)d_in[0];
    const float* cent   = (const float*)d_in[1];
    const float* weight = (const float*)d_in[2];
    const float* bias   = (const float*)d_in[4];
    float* out = (float*)d_out;

    const int ntok = in_sizes[0] / INF;

    const int IDX_SMEM = (128 * 129 + DSUB * KC + 16 * 8 + 16) * (int)sizeof(float);
    const int G_SMEM   = NC * KC * 32 * (int)sizeof(float) + 256 * NC;  // 73728 B

    cudaFuncSetAttribute(idx_kernel,    cudaFuncAttributeMaxDynamicSharedMemorySize, IDX_SMEM);
    cudaFuncSetAttribute(gather_kernel, cudaFuncAttributeMaxDynamicSharedMemorySize, G_SMEM);

    lut_kernel<<<dim3(OF / 256, NC), 128>>>(cent, weight);
    idx_kernel<<<dim3(ntok / 128, NC), 128, IDX_SMEM>>>(x, cent);
    gather_kernel<<<dim3(OF / 32, ntok / 256), 256, G_SMEM>>>(out, bias);
}